// round 2
// baseline (speedup 1.0000x reference)
#include <cuda_runtime.h>
#include <cuda_bf16.h>
#include <cstdint>
#include <math.h>

#define EPSV 1e-5f
#define BATCH 4096
#define HDIM 4096
#define DIN 1024
#define NOUT 2000
#define NOUT_PAD 2048

// ---------------- scratch (device globals: allocation-free) ----------------
__device__ __align__(16) __nv_bfloat16 g_A[BATCH * HDIM];   // quantized activations (int-valued bf16)
__device__ __align__(16) __nv_bfloat16 g_W[HDIM * HDIM];    // ternary weights (bf16 -1/0/1), reused per layer
__device__ float  g_C[BATCH * HDIM];                        // raw GEMM output (integer-valued fp32)
__device__ float  g_rs[BATCH];                              // per-row activation dequant (1/scale)
__device__ double g_wpart[4][2048];                         // per-block partial |W| sums
__device__ double g_wsum[4];                                // total |W| sums

// ---------------- reductions ----------------
__device__ __forceinline__ float blockReduceSum(float val) {
    __shared__ float sm[32];
    int lane = threadIdx.x & 31, wid = threadIdx.x >> 5;
#pragma unroll
    for (int o = 16; o; o >>= 1) val += __shfl_xor_sync(0xffffffffu, val, o);
    if (lane == 0) sm[wid] = val;
    __syncthreads();
    if (wid == 0) {
        val = (lane < (blockDim.x >> 5)) ? sm[lane] : 0.f;
#pragma unroll
        for (int o = 16; o; o >>= 1) val += __shfl_xor_sync(0xffffffffu, val, o);
        if (lane == 0) sm[0] = val;
    }
    __syncthreads();
    float r = sm[0];
    __syncthreads();
    return r;
}

__device__ __forceinline__ float blockReduceMax(float val) {
    __shared__ float sm[32];
    int lane = threadIdx.x & 31, wid = threadIdx.x >> 5;
#pragma unroll
    for (int o = 16; o; o >>= 1) val = fmaxf(val, __shfl_xor_sync(0xffffffffu, val, o));
    if (lane == 0) sm[wid] = val;
    __syncthreads();
    if (wid == 0) {
        val = (lane < (blockDim.x >> 5)) ? sm[lane] : 0.f;
#pragma unroll
        for (int o = 16; o; o >>= 1) val = fmaxf(val, __shfl_xor_sync(0xffffffffu, val, o));
        if (lane == 0) sm[0] = val;
    }
    __syncthreads();
    float r = sm[0];
    __syncthreads();
    return r;
}

// ---------------- weight abs-mean (deterministic two-pass) ----------------
__global__ void wsum_kernel(const float* __restrict__ W, int n, int idx) {
    double s = 0.0;
    for (int i = blockIdx.x * blockDim.x + threadIdx.x; i < n; i += gridDim.x * blockDim.x)
        s += (double)fabsf(W[i]);
    __shared__ double sm[256];
    sm[threadIdx.x] = s;
    __syncthreads();
    for (int o = 128; o; o >>= 1) {
        if (threadIdx.x < o) sm[threadIdx.x] += sm[threadIdx.x + o];
        __syncthreads();
    }
    if (threadIdx.x == 0) g_wpart[idx][blockIdx.x] = sm[0];
}

__global__ void wreduce_kernel() {
    int idx = blockIdx.x;  // one block per weight matrix
    double s = 0.0;
    for (int i = threadIdx.x; i < 2048; i += 256) s += g_wpart[idx][i];
    __shared__ double sm[256];
    sm[threadIdx.x] = s;
    __syncthreads();
    for (int o = 128; o; o >>= 1) {
        if (threadIdx.x < o) sm[threadIdx.x] += sm[threadIdx.x + o];
        __syncthreads();
    }
    if (threadIdx.x == 0) g_wsum[idx] = sm[0];
}

// ---------------- ternarize weights into bf16 scratch ----------------
__global__ void tern_kernel(const float* __restrict__ W, int rows, int cols,
                            int rows_pad, int idx, double count) {
    float mean = (float)(g_wsum[idx] / count);
    float scale = 1.0f / fmaxf(mean, EPSV);
    int n = rows_pad * cols;
    for (int i = blockIdx.x * blockDim.x + threadIdx.x; i < n; i += gridDim.x * blockDim.x) {
        int r = i / cols;
        float t = 0.0f;
        if (r < rows) {
            t = rintf(W[(size_t)i] * scale);  // i == r*cols+c valid while r<rows
            t = fminf(fmaxf(t, -1.0f), 1.0f);
        }
        g_W[i] = __float2bfloat16(t);
    }
}

// ---------------- quantize input x ----------------
__global__ void actquant_x(const float* __restrict__ x) {
    int row = blockIdx.x;
    const float* xr = x + (size_t)row * DIN;
    float m = 0.0f;
    for (int j = threadIdx.x; j < DIN; j += 256) m = fmaxf(m, fabsf(xr[j]));
    m = blockReduceMax(m);
    float scale = 127.0f / fmaxf(m, EPSV);
    for (int j = threadIdx.x; j < DIN; j += 256) {
        float q = rintf(xr[j] * scale);
        q = fminf(fmaxf(q, -128.0f), 127.0f);
        g_A[(size_t)row * DIN + j] = __float2bfloat16(q);
    }
    if (threadIdx.x == 0) g_rs[row] = 1.0f / scale;
}

// ---------------- bf16 tensor-core GEMM: C[M,N] = g_A[M,K] @ g_W[N,K]^T ----------------
// 128x128x32 block tile, 8 warps (2x4), warp tile 64x32, mma.sync m16n8k16 bf16.
__global__ __launch_bounds__(256) void gemm_kernel(int K, int ldc) {
    __shared__ __nv_bfloat16 As[128][40];
    __shared__ __nv_bfloat16 Bs[128][40];
    const int bm = blockIdx.y * 128;
    const int bn = blockIdx.x * 128;
    const int tid = threadIdx.x;
    const int lane = tid & 31;
    const int wid = tid >> 5;
    const int wm = (wid >> 2) * 64;
    const int wn = (wid & 3) * 32;

    float acc[4][4][4];
#pragma unroll
    for (int i = 0; i < 4; i++)
#pragma unroll
        for (int j = 0; j < 4; j++)
#pragma unroll
            for (int k = 0; k < 4; k++) acc[i][j][k] = 0.0f;

    const int lr = tid >> 2;         // 0..63
    const int lc = (tid & 3) * 8;    // 0,8,16,24

    for (int k0 = 0; k0 < K; k0 += 32) {
        uint4 a0v = *(const uint4*)(g_A + (size_t)(bm + lr) * K + k0 + lc);
        uint4 a1v = *(const uint4*)(g_A + (size_t)(bm + lr + 64) * K + k0 + lc);
        uint4 b0v = *(const uint4*)(g_W + (size_t)(bn + lr) * K + k0 + lc);
        uint4 b1v = *(const uint4*)(g_W + (size_t)(bn + lr + 64) * K + k0 + lc);
        *(uint4*)&As[lr][lc] = a0v;
        *(uint4*)&As[lr + 64][lc] = a1v;
        *(uint4*)&Bs[lr][lc] = b0v;
        *(uint4*)&Bs[lr + 64][lc] = b1v;
        __syncthreads();

#pragma unroll
        for (int kk = 0; kk < 32; kk += 16) {
            uint32_t af[4][4];
#pragma unroll
            for (int mi = 0; mi < 4; mi++) {
                int r = wm + mi * 16 + (lane >> 2);
                int c = kk + (lane & 3) * 2;
                af[mi][0] = *(const uint32_t*)&As[r][c];
                af[mi][1] = *(const uint32_t*)&As[r + 8][c];
                af[mi][2] = *(const uint32_t*)&As[r][c + 8];
                af[mi][3] = *(const uint32_t*)&As[r + 8][c + 8];
            }
            uint32_t bfr[4][2];
#pragma unroll
            for (int ni = 0; ni < 4; ni++) {
                int r = wn + ni * 8 + (lane >> 2);
                int c = kk + (lane & 3) * 2;
                bfr[ni][0] = *(const uint32_t*)&Bs[r][c];
                bfr[ni][1] = *(const uint32_t*)&Bs[r][c + 8];
            }
#pragma unroll
            for (int mi = 0; mi < 4; mi++)
#pragma unroll
                for (int ni = 0; ni < 4; ni++)
                    asm volatile(
                        "mma.sync.aligned.m16n8k16.row.col.f32.bf16.bf16.f32 "
                        "{%0,%1,%2,%3}, {%4,%5,%6,%7}, {%8,%9}, {%0,%1,%2,%3};\n"
                        : "+f"(acc[mi][ni][0]), "+f"(acc[mi][ni][1]),
                          "+f"(acc[mi][ni][2]), "+f"(acc[mi][ni][3])
                        : "r"(af[mi][0]), "r"(af[mi][1]), "r"(af[mi][2]), "r"(af[mi][3]),
                          "r"(bfr[ni][0]), "r"(bfr[ni][1]));
        }
        __syncthreads();
    }

#pragma unroll
    for (int mi = 0; mi < 4; mi++) {
#pragma unroll
        for (int ni = 0; ni < 4; ni++) {
            int r = bm + wm + mi * 16 + (lane >> 2);
            int c = bn + wn + ni * 8 + (lane & 3) * 2;
            g_C[(size_t)r * ldc + c]         = acc[mi][ni][0];
            g_C[(size_t)r * ldc + c + 1]     = acc[mi][ni][1];
            g_C[(size_t)(r + 8) * ldc + c]     = acc[mi][ni][2];
            g_C[(size_t)(r + 8) * ldc + c + 1] = acc[mi][ni][3];
        }
    }
}

// ---------------- fused scale + LayerNorm + SiLU + re-quantize ----------------
__global__ void ln_silu_quant(const float* __restrict__ gamma, const float* __restrict__ beta,
                              int widx, double count) {
    int row = blockIdx.x;
    float wmean = fmaxf((float)(g_wsum[widx] / count), EPSV);
    float f = g_rs[row] * wmean;
    const float* cr = g_C + (size_t)row * HDIM;

    float v[16];
    float s = 0.0f;
#pragma unroll
    for (int i = 0; i < 16; i++) {
        v[i] = cr[threadIdx.x + i * 256] * f;
        s += v[i];
    }
    s = blockReduceSum(s);
    float mu = s * (1.0f / HDIM);

    float s2 = 0.0f;
#pragma unroll
    for (int i = 0; i < 16; i++) {
        float d = v[i] - mu;
        s2 += d * d;
    }
    s2 = blockReduceSum(s2);
    float inv_std = 1.0f / sqrtf(s2 * (1.0f / HDIM) + EPSV);

    float y[16];
    float mx = 0.0f;
#pragma unroll
    for (int i = 0; i < 16; i++) {
        int j = threadIdx.x + i * 256;
        float t = (v[i] - mu) * inv_std * gamma[j] + beta[j];
        t = t / (1.0f + expf(-t));  // silu
        y[i] = t;
        mx = fmaxf(mx, fabsf(t));
    }
    mx = blockReduceMax(mx);
    float scale = 127.0f / fmaxf(mx, EPSV);
#pragma unroll
    for (int i = 0; i < 16; i++) {
        int j = threadIdx.x + i * 256;
        float q = rintf(y[i] * scale);
        q = fminf(fmaxf(q, -128.0f), 127.0f);
        g_A[(size_t)row * HDIM + j] = __float2bfloat16(q);
    }
    if (threadIdx.x == 0) g_rs[row] = 1.0f / scale;
}

// ---------------- final sigmoid split ----------------
__global__ void final_kernel(float* __restrict__ out, double count) {
    int idx = blockIdx.x * blockDim.x + threadIdx.x;
    if (idx >= BATCH * 1000) return;
    int row = idx / 1000;
    int j = idx - row * 1000;
    float wmean = fmaxf((float)(g_wsum[3] / count), EPSV);
    float f = g_rs[row] * wmean;
    float l1 = g_C[(size_t)row * NOUT_PAD + j] * f;
    float l2 = g_C[(size_t)row * NOUT_PAD + 1000 + j] * f;
    float mz = 999.0f / (1.0f + expf(-l1)) + 1.0f;
    float it = 100.0f / (1.0f + expf(-l2));
    out[(size_t)row * 1000 + j] = mz;
    out[(size_t)BATCH * 1000 + (size_t)row * 1000 + j] = it;
}

// ---------------- launch ----------------
extern "C" void kernel_launch(void* const* d_in, const int* in_sizes, int n_in,
                              void* d_out, int out_size) {
    const float* x  = (const float*)d_in[0];
    const float* W0 = (const float*)d_in[1];
    const float* W1 = (const float*)d_in[2];
    const float* W2 = (const float*)d_in[3];
    const float* W3 = (const float*)d_in[4];
    const float* g0 = (const float*)d_in[5];
    const float* b0 = (const float*)d_in[6];
    const float* g1 = (const float*)d_in[7];
    const float* b1 = (const float*)d_in[8];
    const float* g2 = (const float*)d_in[9];
    const float* b2 = (const float*)d_in[10];
    float* out = (float*)d_out;

    const double c0 = (double)HDIM * DIN;      // 4,194,304
    const double c1 = (double)HDIM * HDIM;     // 16,777,216
    const double c3 = (double)NOUT * HDIM;     // 8,192,000

    // Weight abs-mean reductions (deterministic two-pass)
    wsum_kernel<<<2048, 256>>>(W0, HDIM * DIN, 0);
    wsum_kernel<<<2048, 256>>>(W1, HDIM * HDIM, 1);
    wsum_kernel<<<2048, 256>>>(W2, HDIM * HDIM, 2);
    wsum_kernel<<<2048, 256>>>(W3, NOUT * HDIM, 3);
    wreduce_kernel<<<4, 256>>>();

    // Quantize input activations
    actquant_x<<<BATCH, 256>>>(x);

    // Layer 0: [4096,1024] @ [4096,1024]^T
    tern_kernel<<<4096, 256>>>(W0, HDIM, DIN, HDIM, 0, c0);
    gemm_kernel<<<dim3(HDIM / 128, BATCH / 128), 256>>>(DIN, HDIM);
    ln_silu_quant<<<BATCH, 256>>>(g0, b0, 0, c0);

    // Layer 1
    tern_kernel<<<4096, 256>>>(W1, HDIM, HDIM, HDIM, 1, c1);
    gemm_kernel<<<dim3(HDIM / 128, BATCH / 128), 256>>>(HDIM, HDIM);
    ln_silu_quant<<<BATCH, 256>>>(g1, b1, 1, c1);

    // Layer 2
    tern_kernel<<<4096, 256>>>(W2, HDIM, HDIM, HDIM, 2, c1);
    gemm_kernel<<<dim3(HDIM / 128, BATCH / 128), 256>>>(HDIM, HDIM);
    ln_silu_quant<<<BATCH, 256>>>(g2, b2, 2, c1);

    // Layer 3: output head, N padded 2000 -> 2048 with zero rows
    tern_kernel<<<4096, 256>>>(W3, NOUT, HDIM, NOUT_PAD, 3, c3);
    gemm_kernel<<<dim3(NOUT_PAD / 128, BATCH / 128), 256>>>(HDIM, NOUT_PAD);
    final_kernel<<<(BATCH * 1000 + 255) / 256, 256>>>(out, c3);
}